// round 14
// baseline (speedup 1.0000x reference)
#include <cuda_runtime.h>
#include <cuda_bf16.h>
#include <cstdint>

// density[b,h,w] = sum_n gy[b,n,h] * gx[b,n,w]
// B=4, N=64, H=W=512. Single fused kernel.
// R8 lesson: occupancy was GRID-limited (256 CTAs -> 14 warps/SM, issue 40%).
// R9: 512 CTAs x 256 thr (tile 64w x 32h) -> ~27.7 warps/SM.
//     Warp covers a SQUARE 16w x 16h footprint (4x2 lanes of 4w x 2h
//     micro-tiles) -> 192B unique smem bytes per warp per n (crossbar
//     dedups broadcasts) ~ 2.7K cyc/SM total, under the 3.5K FMA2 floor.
// Per n-step per thread: 1 LDS.128 gx + 1 LDS.128 gy-dup + 4 fma.rn.f32x2.

#define B_  4
#define N_  64
#define HW_ 512
#define TW_ 64
#define TH_ 32
#define KP_ 16            // n per pass
#define NP_ 4             // passes

#define FMA2(d, a, bb, c) \
    asm("fma.rn.f32x2 %0, %1, %2, %3;" : "=l"(d) : "l"(a), "l"(bb), "l"(c))

__global__ __launch_bounds__(256, 4) void density_kernel(
    float* __restrict__ out,
    const float* __restrict__ labels,   // (B, N, 2)
    const float* __restrict__ sigma)    // (1,)
{
    __shared__ float  sGx[2][KP_ * TW_];    // 2 x 4 KB, [n][w], pre-scaled
    __shared__ float2 sGy[2][KP_ * TH_];    // 2 x 4 KB, [n][h], (v,v) dup
    __shared__ float  sLx[N_], sLy[N_];
    __shared__ float  sSum[2 * N_];         // [0,64)=x sums, [64,128)=y sums
    __shared__ float  sInv[N_];             // 1 / (sum_x * sum_y)

    const int b     = blockIdx.z;
    const int wbase = blockIdx.x * TW_;
    const int hbase = blockIdx.y * TH_;
    const int t     = threadIdx.x;

    const float sg  = sigma[0];
    const float inv = 0.5f / (sg * sg);   // 1/(2 sigma^2)

    if (t < N_) {
        const float2 l = ((const float2*)labels)[b * N_ + t];
        sLx[t] = l.x;
        sLy[t] = l.y;
    }
    __syncthreads();

    // ---- Phase 0: adaptive-window row sums. 2 threads/row, nh px each. ----
    {
        const int r    = t >> 1;          // 0..127 (row: axis*64 + n)
        const int half = t & 1;
        const float c  = (r < N_) ? sLx[r] : sLy[r - N_];
        const int nh   = min(256, max(16, (int)(7.0f * sg)));  // 7 sigma
        const int ci   = __float2int_rn(c);
        const int s0   = min(max(ci - nh, 0), HW_ - 2 * nh);
        const int beg  = s0 + half * nh;

        float s0a = 0.0f, s1a = 0.0f;
        int i = 0;
        for (; i + 1 < nh; i += 2) {
            const float d0 = (float)(beg + i)     - c;
            const float d1 = (float)(beg + i + 1) - c;
            s0a += __expf(-(d0 * d0) * inv);
            s1a += __expf(-(d1 * d1) * inv);
        }
        if (i < nh) {
            const float d0 = (float)(beg + i) - c;
            s0a += __expf(-(d0 * d0) * inv);
        }
        float s = s0a + s1a;
        s += __shfl_xor_sync(0xFFFFFFFFu, s, 1);
        if (half == 0) sSum[r] = s;
    }
    __syncthreads();
    if (t < N_)
        sInv[t] = __fdividef(1.0f, sSum[t] * sSum[N_ + t]);
    __syncthreads();

    // ---- thread geometry: warp = 16w x 16h square footprint ----
    const int lane   = t & 31;
    const int wid    = t >> 5;            // 0..7
    const int warp_w = wid & 3;           // 4 warps across w (x16)
    const int warp_h = wid >> 2;          // 2 warps across h (x16)
    const int lane_w = lane & 3;          // 4 lanes across w (x4)
    const int lane_h = lane >> 2;         // 8 lanes across h (x2)
    const int ix     = warp_w * 4 + lane_w;   // gx ull2 index within n-row
    const int iy     = warp_h * 8 + lane_h;   // gy ull2 index within n-row
    const int w0     = ix * 4;            // thread's first w (4 wide)
    const int h0     = iy * 2;            // thread's first h (2 tall)

    unsigned long long acc00 = 0ull, acc01 = 0ull;   // h0: w-pairs 0,1
    unsigned long long acc10 = 0ull, acc11 = 0ull;   // h0+1

    // tile generator: pass p -> labels [p*KP_, (p+1)*KP_), buffer buf
    auto gen = [&](int p, int buf) {
        const int n0 = p * KP_;
        #pragma unroll
        for (int i = t; i < KP_ * TW_; i += 256) {     // gx scaled: 4/thread
            const int n = i >> 6;
            const float d = (float)(wbase + (i & 63)) - sLx[n0 + n];
            sGx[buf][i] = __expf(-(d * d) * inv) * sInv[n0 + n];
        }
        #pragma unroll
        for (int i = t; i < KP_ * TH_; i += 256) {     // gy dup: 2/thread
            const int n = i >> 5;
            const float d = (float)(hbase + (i & 31)) - sLy[n0 + n];
            const float v = __expf(-(d * d) * inv);
            sGy[buf][i] = make_float2(v, v);
        }
    };

    gen(0, 0);
    __syncthreads();

    // ---- pipelined mainloop: gen(p+1) overlaps fma(p) ----
    #pragma unroll
    for (int p = 0; p < NP_; p++) {
        const int buf = p & 1;
        if (p + 1 < NP_) gen(p + 1, buf ^ 1);

        const ulonglong2* sxp = (const ulonglong2*)sGx[buf];  // 16 ull2 /n-row
        const ulonglong2* syp = (const ulonglong2*)sGy[buf];  // 16 ull2 /n-row

        #pragma unroll 8
        for (int n = 0; n < KP_; n++) {
            const ulonglong2 bx = sxp[n * 16 + ix];   // 4 gx (2 f32x2 pairs)
            const ulonglong2 ay = syp[n * 16 + iy];   // gy h0,h0 | h1,h1

            FMA2(acc00, ay.x, bx.x, acc00);
            FMA2(acc01, ay.x, bx.y, acc01);
            FMA2(acc10, ay.y, bx.x, acc10);
            FMA2(acc11, ay.y, bx.y, acc11);
        }
        if (p + 1 < NP_) __syncthreads();  // gen(p+2) may overwrite buf
    }

    // ---- Store: 2 h-rows x 4 consecutive floats = 2x STG.128 ----
    {
        float4 r0, r1;
        r0.x = ((const float*)&acc00)[0]; r0.y = ((const float*)&acc00)[1];
        r0.z = ((const float*)&acc01)[0]; r0.w = ((const float*)&acc01)[1];
        r1.x = ((const float*)&acc10)[0]; r1.y = ((const float*)&acc10)[1];
        r1.z = ((const float*)&acc11)[0]; r1.w = ((const float*)&acc11)[1];

        const int h = hbase + h0;
        const int w = wbase + w0;
        float* base = out + ((size_t)b * HW_ + h) * HW_ + w;
        *(float4*)(base)       = r0;
        *(float4*)(base + HW_) = r1;
    }
}

// ---------------------------------------------------------------------------
// Launch: single kernel, single graph node.
// ---------------------------------------------------------------------------
extern "C" void kernel_launch(void* const* d_in, const int* in_sizes, int n_in,
                              void* d_out, int out_size)
{
    // d_in[0] = batch_images (unused, shape only)
    const float* labels = (const float*)d_in[1];  // (4, 64, 2)
    const float* sigma  = (const float*)d_in[2];  // (1,)
    float* out = (float*)d_out;                   // (4, 1, 512, 512)

    dim3 grid(HW_ / TW_, HW_ / TH_, B_);   // (8, 16, 4) = 512 CTAs
    density_kernel<<<grid, 256>>>(out, labels, sigma);
}